// round 13
// baseline (speedup 1.0000x reference)
#include <cuda_runtime.h>
#include <cuda_bf16.h>
#include <cstdint>
#include <math.h>

// ---------------- problem constants ----------------
#define INV_TAU (1.0f / 0.07f)
constexpr int Bb = 16, Ll = 32, Dd = 256, Kk = 131072;
constexpr int Nn = 512;          // B*L frames
constexpr int NQ = 528;          // 512 z rows + 16 g rows
constexpr int NQP = 576;         // padded to 6*96
constexpr int BM = 96, BN = 128, BK = 32;
constexpr int NT_Q = Kk / BN;    // 1024 queue tiles
constexpr int NT_Z = Nn / BN;    // 4 z-key tiles
constexpr int NT = NT_Q + NT_Z;  // 1028
constexpr int MT = NQP / BM;     // 6
constexpr int MLL = Bb * (Ll - 1);

// smem layout: A fp32 pitch 40 words (160B rows), B fp32 pitch 40; 3 stages
constexpr int APB = 40;                       // words per row slot
constexpr int A_BYTES = BM * APB * 4;         // 15360 per stage (fp32 now)
constexpr int B_BYTES = BN * APB * 4;         // 20480 per stage
constexpr int OFF_B = 3 * A_BYTES;            // 46080
constexpr int OFF_RED = OFF_B + 3 * B_BYTES;  // 107520
constexpr int SMEM_BYTES = OFF_RED + BM * 4 * 4 * 2;  // 110592 (108KB/CTA, 216KB/SM)

// ---------------- device scratch ----------------
__device__ float d_part[NQP * NT_Q];
__device__ float d_Sim[NQP * Nn];
__device__ float d_llterms[MLL];
__device__ float d_glterms[Nn];
__device__ float d_smterms[Nn];               // per-frame smoothness partials
__device__ int d_done;                        // k_post completion counter

// ---------------- helpers ----------------
__device__ __forceinline__ void mma16(float4& d, const uint32_t* a, const uint32_t* b) {
    asm volatile(
        "mma.sync.aligned.m16n8k16.row.col.f32.bf16.bf16.f32 "
        "{%0,%1,%2,%3}, {%4,%5,%6,%7}, {%8,%9}, {%0,%1,%2,%3};\n"
        : "+f"(d.x), "+f"(d.y), "+f"(d.z), "+f"(d.w)
        : "r"(a[0]), "r"(a[1]), "r"(a[2]), "r"(a[3]), "r"(b[0]), "r"(b[1]));
}
__device__ __forceinline__ void cpasync16(uint32_t dst, const void* src) {
    asm volatile("cp.async.cg.shared.global [%0], [%1], 16;\n" :: "r"(dst), "l"(src));
}
__device__ __forceinline__ float softplusf(float x) {
    return (x > 0.f) ? x + log1pf(expf(-x)) : log1pf(expf(x));
}
__device__ __forceinline__ uint32_t bf2_bits(float lo, float hi) {
    __nv_bfloat162 p = __float22bfloat162_rn(make_float2(lo, hi));
    return *reinterpret_cast<uint32_t*>(&p);
}

// ---------------- kernel 1: 3-stage pipelined bf16 GEMM, 2 CTAs/SM, inline cvt ----------------
__global__ __launch_bounds__(256, 2) void k_gemm(const float* __restrict__ mq,
                                                 const float* __restrict__ z,
                                                 const float* __restrict__ g) {
    extern __shared__ char smc[];
    const uint32_t smem_u32 = (uint32_t)__cvta_generic_to_shared(smc);

    const int tid  = threadIdx.x;
    const int warp = tid >> 5, lane = tid & 31;
    const int wm = warp >> 2, wn = warp & 3;   // 2 x 4 warp grid (48 rows x 32 cols each)
    const int g8 = lane >> 2, tg = lane & 3;
    const int mtile = blockIdx.x;
    const int ntile = blockIdx.y;
    const bool is_z = (ntile >= NT_Q);

    if (mtile == 0 && ntile == 0 && tid == 0) d_done = 0;   // reset fusion counter

    // A source rows: z frames [0,512), g rows [512,528), pad rows alias z row 0
    // (pad results are discarded by the grow<NQ guard / never-read d_Sim rows).
    const float* asrc[3];
    uint32_t adst[3];
#pragma unroll
    for (int i = 0; i < 3; i++) {
        const int id = tid + i * 256;              // 0..767
        const int r = id >> 3, c4 = id & 7;
        const int grow = mtile * BM + r;
        const float* base = (grow < Nn) ? (z + grow * Dd)
                          : (grow < NQ) ? (g + (grow - Nn) * Dd)
                                        : z;
        asrc[i] = base + c4 * 4;
        adst[i] = smem_u32 + (r * APB + c4 * 4) * 4;
    }
    const float* Kb = is_z ? (z + (size_t)(ntile - NT_Q) * BN * Dd)
                           : (mq + (size_t)ntile * BN * Dd);
    const float* bsrc[4];
    uint32_t bdst[4];
#pragma unroll
    for (int i = 0; i < 4; i++) {
        const int id = tid + i * 256;
        const int r = id >> 3, c4 = id & 7;
        bsrc[i] = Kb + r * Dd + c4 * 4;
        bdst[i] = smem_u32 + OFF_B + (r * APB + c4 * 4) * 4;
    }

    float4 acc[3][4];
#pragma unroll
    for (int mi = 0; mi < 3; mi++)
#pragma unroll
        for (int ni = 0; ni < 4; ni++) acc[mi][ni] = make_float4(0.f, 0.f, 0.f, 0.f);

#define LOAD_STAGE(s, kk)                                                    \
    do {                                                                     \
        _Pragma("unroll")                                                    \
        for (int i = 0; i < 3; i++)                                          \
            cpasync16(adst[i] + (s) * A_BYTES, asrc[i] + (kk) * BK);         \
        _Pragma("unroll")                                                    \
        for (int i = 0; i < 4; i++)                                          \
            cpasync16(bdst[i] + (s) * B_BYTES, bsrc[i] + (kk) * BK);         \
    } while (0)

    LOAD_STAGE(0, 0);
    asm volatile("cp.async.commit_group;\n");
    LOAD_STAGE(1, 1);
    asm volatile("cp.async.commit_group;\n");

#pragma unroll
    for (int kk = 0; kk < 8; kk++) {
        asm volatile("cp.async.wait_group 1;\n");
        __syncthreads();
        const int s = kk % 3;
        if (kk + 2 < 8) {
            LOAD_STAGE((kk + 2) % 3, kk + 2);
        }
        asm volatile("cp.async.commit_group;\n");

        const float* As = (const float*)(smc + s * A_BYTES);
        const float* Bs = (const float*)(smc + OFF_B + s * B_BYTES);

#pragma unroll
        for (int ks = 0; ks < 2; ks++) {
            const int k0 = ks * 16;
            uint32_t a[3][4];
#pragma unroll
            for (int mi = 0; mi < 3; mi++) {
                const int r0 = (wm * 48 + mi * 16 + g8) * APB;
                float2 a0 = *(const float2*)&As[r0 + k0 + tg * 2];
                float2 a1 = *(const float2*)&As[r0 + 8 * APB + k0 + tg * 2];
                float2 a2 = *(const float2*)&As[r0 + k0 + tg * 2 + 8];
                float2 a3 = *(const float2*)&As[r0 + 8 * APB + k0 + tg * 2 + 8];
                a[mi][0] = bf2_bits(a0.x, a0.y);
                a[mi][1] = bf2_bits(a1.x, a1.y);
                a[mi][2] = bf2_bits(a2.x, a2.y);
                a[mi][3] = bf2_bits(a3.x, a3.y);
            }
            uint32_t b[4][2];
#pragma unroll
            for (int ni = 0; ni < 4; ni++) {
                const float* bp = &Bs[(wn * 32 + ni * 8 + g8) * APB + k0 + tg * 2];
                float2 v0 = *(const float2*)bp;
                float2 v1 = *(const float2*)(bp + 8);
                b[ni][0] = bf2_bits(v0.x * INV_TAU, v0.y * INV_TAU);
                b[ni][1] = bf2_bits(v1.x * INV_TAU, v1.y * INV_TAU);
            }
#pragma unroll
            for (int mi = 0; mi < 3; mi++)
#pragma unroll
                for (int ni = 0; ni < 4; ni++) mma16(acc[mi][ni], a[mi], b[ni]);
        }
    }
#undef LOAD_STAGE

    if (!is_z) {
        // ---- per-row lse over this 128-col tile ----
        float* red_m = (float*)(smc + OFF_RED);
        float* red_s = red_m + BM * 4;
#pragma unroll
        for (int mi = 0; mi < 3; mi++) {
#pragma unroll
            for (int half = 0; half < 2; half++) {
                float v[8];
#pragma unroll
                for (int ni = 0; ni < 4; ni++) {
                    v[2 * ni]     = half ? acc[mi][ni].z : acc[mi][ni].x;
                    v[2 * ni + 1] = half ? acc[mi][ni].w : acc[mi][ni].y;
                }
                float m = v[0];
#pragma unroll
                for (int i = 1; i < 8; i++) m = fmaxf(m, v[i]);
                float s = 0.f;
#pragma unroll
                for (int i = 0; i < 8; i++) s += __expf(v[i] - m);
#pragma unroll
                for (int o = 1; o < 4; o <<= 1) {
                    float om = __shfl_xor_sync(0xffffffffu, m, o);
                    float os = __shfl_xor_sync(0xffffffffu, s, o);
                    float nm = fmaxf(m, om);
                    s = s * __expf(m - nm) + os * __expf(om - nm);
                    m = nm;
                }
                if (tg == 0) {
                    int rl = wm * 48 + mi * 16 + half * 8 + g8;
                    red_m[rl * 4 + wn] = m;
                    red_s[rl * 4 + wn] = s;
                }
            }
        }
        __syncthreads();
        if (tid < BM) {
            float m = red_m[tid * 4], s = red_s[tid * 4];
#pragma unroll
            for (int w = 1; w < 4; w++) {
                float om = red_m[tid * 4 + w], os = red_s[tid * 4 + w];
                float nm = fmaxf(m, om);
                s = s * __expf(m - nm) + os * __expf(om - nm);
                m = nm;
            }
            int grow = mtile * BM + tid;
            if (grow < NQ) d_part[grow * NT_Q + ntile] = m + __logf(s);
        }
    } else {
        // ---- write raw sims for the z-key tiles ----
        const int col0 = (ntile - NT_Q) * BN + wn * 32;
#pragma unroll
        for (int mi = 0; mi < 3; mi++) {
            const int row0 = mtile * BM + wm * 48 + mi * 16 + g8;
#pragma unroll
            for (int ni = 0; ni < 4; ni++) {
                const int c = col0 + ni * 8 + 2 * tg;
                *(float2*)&d_Sim[row0 * Nn + c]       = make_float2(acc[mi][ni].x, acc[mi][ni].y);
                *(float2*)&d_Sim[(row0 + 8) * Nn + c] = make_float2(acc[mi][ni].z, acc[mi][ni].w);
            }
        }
    }
}

// ---------------- kernel 2: fused reduce + masked lse + combine + smoothness + final ----------------
__global__ void k_post(const float* __restrict__ z, float* __restrict__ out) {
    __shared__ float rm[256], rs[256];
    __shared__ float posbuf[Ll];
    __shared__ float s_pos, s_lseq, s_lse;
    __shared__ int s_last;
    const int bid = blockIdx.x, tid = threadIdx.x;
    const bool is_g = (bid >= Nn);
    const int a = bid, gb = bid - Nn;

    // ---- phase A: lse over 1024 queue partials ----
    const float* p = d_part + bid * NT_Q;
    float vals[4];
    float m = -INFINITY;
#pragma unroll
    for (int i = 0; i < 4; i++) { vals[i] = p[tid + i * 256]; m = fmaxf(m, vals[i]); }
    rm[tid] = m; __syncthreads();
    for (int st = 128; st; st >>= 1) {
        if (tid < st) rm[tid] = fmaxf(rm[tid], rm[tid + st]);
        __syncthreads();
    }
    const float M = rm[0]; __syncthreads();
    float s = 0.f;
#pragma unroll
    for (int i = 0; i < 4; i++) s += __expf(vals[i] - M);
    rs[tid] = s; __syncthreads();
    for (int st = 128; st; st >>= 1) {
        if (tid < st) rs[tid] += rs[tid + st];
        __syncthreads();
    }
    if (tid == 0) s_lseq = M + __logf(rs[0]);
    __syncthreads();

    // ---- phase B: masked lse over the 512 precomputed sims ----
    float mm = -INFINITY, sacc = 0.f;
#pragma unroll
    for (int rep = 0; rep < 2; rep++) {
        const int j = tid + rep * 256;
        const float v = d_Sim[bid * Nn + j];
        bool masked = false;
        if (is_g) { if ((j >> 5) == gb) { posbuf[j & 31] = v; masked = true; } }
        else {
            if (j == a) masked = true;
            else if (j == a + 1) { s_pos = v; masked = true; }
        }
        if (!masked) {
            if (v > mm) { sacc = sacc * expf(mm - v) + 1.f; mm = v; }
            else        { sacc += expf(v - mm); }
        }
    }
    rm[tid] = mm; rs[tid] = sacc;
    __syncthreads();
    for (int st = 128; st; st >>= 1) {
        if (tid < st) {
            float m1 = rm[tid], s1 = rs[tid];
            float m2 = rm[tid + st], s2 = rs[tid + st];
            float nm = fmaxf(m1, m2);
            float ns = (nm == -INFINITY) ? 0.f : s1 * expf(m1 - nm) + s2 * expf(m2 - nm);
            rm[tid] = nm; rs[tid] = ns;
        }
        __syncthreads();
    }
    if (tid == 0) {
        const float lneg = rm[0] + logf(rs[0]);
        const float lq = s_lseq;
        const float hi = fmaxf(lneg, lq), lo = fminf(lneg, lq);
        s_lse = hi + log1pf(expf(lo - hi));
    }
    __syncthreads();
    if (!is_g) {
        const int t = a & (Ll - 1);
        if (t < Ll - 1 && tid == 0)
            d_llterms[(a >> 5) * (Ll - 1) + t] = softplusf(s_lse - s_pos);
    } else {
        if (tid < Ll) d_glterms[gb * Ll + tid] = softplusf(s_lse - posbuf[tid]);
    }

    // ---- phase C: per-frame smoothness partial (z blocks with t < Ll-1) ----
    if (!is_g && (a & (Ll - 1)) < Ll - 1) {
        const float df = z[(a + 1) * Dd + tid] - z[a * Dd + tid];
        __syncthreads();
        rm[tid] = df * df;
        __syncthreads();
        for (int st = 128; st; st >>= 1) {
            if (tid < st) rm[tid] += rm[tid + st];
            __syncthreads();
        }
        if (tid == 0) {
            const int t = a & (Ll - 1);
            d_smterms[(a >> 5) * (Ll - 1) + t] = rm[0];
        }
    }

    // ---- phase D: last block computes the final scalar ----
    __threadfence();
    __syncthreads();
    if (tid == 0) s_last = (atomicAdd(&d_done, 1) == NQ - 1);
    __syncthreads();
    if (s_last) {
        __threadfence();
        float sll = 0.f, sgl = 0.f, ssm = 0.f;
        for (int i = tid; i < MLL; i += 256) { sll += d_llterms[i]; ssm += d_smterms[i]; }
        for (int i = tid; i < Nn; i += 256) sgl += d_glterms[i];
        float Sll, Sgl, Ssm;
        rm[tid] = sll; __syncthreads();
        for (int st = 128; st; st >>= 1) { if (tid < st) rm[tid] += rm[tid + st]; __syncthreads(); }
        Sll = rm[0]; __syncthreads();
        rm[tid] = sgl; __syncthreads();
        for (int st = 128; st; st >>= 1) { if (tid < st) rm[tid] += rm[tid + st]; __syncthreads(); }
        Sgl = rm[0]; __syncthreads();
        rm[tid] = ssm; __syncthreads();
        for (int st = 128; st; st >>= 1) { if (tid < st) rm[tid] += rm[tid + st]; __syncthreads(); }
        Ssm = rm[0];
        if (tid == 0)
            out[0] = Sll / (float)MLL + 0.5f * (Sgl / (float)Nn) + 0.1f * (Ssm / (float)MLL);
    }
}

// ---------------- launch ----------------
extern "C" void kernel_launch(void* const* d_in, const int* in_sizes, int n_in,
                              void* d_out, int out_size) {
    const float* z  = (const float*)d_in[0];
    const float* g  = (const float*)d_in[1];
    const float* mq = (const float*)d_in[3];
    float* out = (float*)d_out;

    cudaFuncSetAttribute(k_gemm, cudaFuncAttributeMaxDynamicSharedMemorySize, SMEM_BYTES);

    dim3 grid(MT, NT);     // mtile fastest -> the 6 blocks sharing a key tile run together
    k_gemm<<<grid, 256, SMEM_BYTES>>>(mq, z, g);
    k_post<<<NQ, 256>>>(z, out);
}

// round 14
// speedup vs baseline: 1.1361x; 1.1361x over previous
#include <cuda_runtime.h>
#include <cuda_bf16.h>
#include <cstdint>
#include <math.h>

// ---------------- problem constants ----------------
#define INV_TAU (1.0f / 0.07f)
constexpr int Bb = 16, Ll = 32, Dd = 256, Kk = 131072;
constexpr int Nn = 512;          // B*L frames
constexpr int NQ = 528;          // 512 z rows + 16 g rows
constexpr int NQP = 576;         // padded to 6*96
constexpr int BM = 96, BN = 128, BK = 32;
constexpr int NT_Q = Kk / BN;    // 1024 queue tiles
constexpr int NT_Z = Nn / BN;    // 4 z-key tiles
constexpr int NT = NT_Q + NT_Z;  // 1028
constexpr int MT = NQP / BM;     // 6
constexpr int MLL = Bb * (Ll - 1);

// smem layout: A bf16 pitch 40 (80B rows), B fp32 pitch 40 (160B rows); 3 stages
constexpr int APB = 40;                       // elems per row slot
constexpr int A_BYTES = BM * APB * 2;         // 7680 per stage
constexpr int B_BYTES = BN * APB * 4;         // 20480 per stage (fp32)
constexpr int OFF_B = 3 * A_BYTES;            // 23040
constexpr int OFF_RED = OFF_B + 3 * B_BYTES;  // 84480
constexpr int SMEM_BYTES = OFF_RED + BM * 4 * 4 * 2;  // + red[96][4]x2 = 87552 (85.5KB)

// ---------------- device scratch ----------------
__device__ __nv_bfloat16 d_Qbuf[NQP * Dd];    // scaled bf16 queries
__device__ float d_part[NQP * NT_Q];
__device__ float d_Sim[NQP * Nn];
__device__ float d_llterms[MLL];
__device__ float d_glterms[Nn];
__device__ float d_smterms[Nn];               // per-frame smoothness partials
__device__ int d_done;                        // k_post completion counter

// ---------------- helpers ----------------
__device__ __forceinline__ void mma16(float4& d, const uint32_t* a, const uint32_t* b) {
    asm volatile(
        "mma.sync.aligned.m16n8k16.row.col.f32.bf16.bf16.f32 "
        "{%0,%1,%2,%3}, {%4,%5,%6,%7}, {%8,%9}, {%0,%1,%2,%3};\n"
        : "+f"(d.x), "+f"(d.y), "+f"(d.z), "+f"(d.w)
        : "r"(a[0]), "r"(a[1]), "r"(a[2]), "r"(a[3]), "r"(b[0]), "r"(b[1]));
}
__device__ __forceinline__ void cpasync16(uint32_t dst, const void* src) {
    asm volatile("cp.async.cg.shared.global [%0], [%1], 16;\n" :: "r"(dst), "l"(src));
}
__device__ __forceinline__ float softplusf(float x) {
    return (x > 0.f) ? x + log1pf(expf(-x)) : log1pf(expf(x));
}
__device__ __forceinline__ uint32_t bf2_bits(float lo, float hi) {
    __nv_bfloat162 p = __float22bfloat162_rn(make_float2(lo, hi));
    return *reinterpret_cast<uint32_t*>(&p);
}

// ---------------- kernel 1: queries (scaled) -> bf16 (vectorized) ----------------
__global__ void k_prep(const float* __restrict__ z, const float* __restrict__ g) {
    const int i = blockIdx.x * blockDim.x + threadIdx.x;   // handles 4 elems
    if (i == 0) d_done = 0;                                // reset fusion counter
    const int e = i * 4;
    const int row = e >> 8, d = e & 255;
    float4 v = make_float4(0.f, 0.f, 0.f, 0.f);
    if (row < Nn)       v = *(const float4*)(z + e);
    else if (row < NQ)  v = *(const float4*)(g + (row - Nn) * Dd + d);
    v.x *= INV_TAU; v.y *= INV_TAU; v.z *= INV_TAU; v.w *= INV_TAU;
    uint2 o;
    o.x = bf2_bits(v.x, v.y);
    o.y = bf2_bits(v.z, v.w);
    *(uint2*)(d_Qbuf + e) = o;
}

// ---------------- kernel 2: 3-stage pipelined bf16 GEMM, 2 CTAs/SM ----------------
__global__ __launch_bounds__(256, 2) void k_gemm(const float* __restrict__ mq,
                                                 const float* __restrict__ zk) {
    extern __shared__ char smc[];
    const uint32_t smem_u32 = (uint32_t)__cvta_generic_to_shared(smc);

    const int tid  = threadIdx.x;
    const int warp = tid >> 5, lane = tid & 31;
    const int wm = warp >> 2, wn = warp & 3;   // 2 x 4 warp grid (48 rows x 32 cols each)
    const int g8 = lane >> 2, tg = lane & 3;
    const int mtile = blockIdx.x;
    const int ntile = blockIdx.y;
    const bool is_z = (ntile >= NT_Q);

    const __nv_bfloat16* Qb = d_Qbuf + mtile * BM * Dd;
    const float* Kb = is_z ? (zk + (size_t)(ntile - NT_Q) * BN * Dd)
                           : (mq + (size_t)ntile * BN * Dd);

    float4 acc[3][4];
#pragma unroll
    for (int mi = 0; mi < 3; mi++)
#pragma unroll
        for (int ni = 0; ni < 4; ni++) acc[mi][ni] = make_float4(0.f, 0.f, 0.f, 0.f);

    // A: 96x32 bf16 = 384 x16B (1.5/thread). B: 128x32 fp32 = 1024 x16B (4/thread).
#define LOAD_STAGE(s, kk)                                                            \
    do {                                                                             \
        _Pragma("unroll")                                                            \
        for (int i = 0; i < 2; i++) {                                                \
            int id = tid + i * 256;                                                  \
            if (id < 384) {                                                          \
                int r = id >> 2, c8 = id & 3;                                        \
                uint32_t dst = smem_u32 + (s) * A_BYTES + (r * APB + c8 * 8) * 2;    \
                cpasync16(dst, Qb + r * Dd + (kk) * BK + c8 * 8);                    \
            }                                                                        \
        }                                                                            \
        _Pragma("unroll")                                                            \
        for (int i = 0; i < 4; i++) {                                                \
            int id = tid + i * 256; int r = id >> 3, c4 = id & 7;                    \
            uint32_t dst = smem_u32 + OFF_B + (s) * B_BYTES + (r * APB + c4 * 4) * 4; \
            cpasync16(dst, Kb + r * Dd + (kk) * BK + c4 * 4);                        \
        }                                                                            \
    } while (0)

    LOAD_STAGE(0, 0);
    asm volatile("cp.async.commit_group;\n");
    LOAD_STAGE(1, 1);
    asm volatile("cp.async.commit_group;\n");

#pragma unroll
    for (int kk = 0; kk < 8; kk++) {
        asm volatile("cp.async.wait_group 1;\n");
        __syncthreads();
        const int s = kk % 3;
        if (kk + 2 < 8) {
            LOAD_STAGE((kk + 2) % 3, kk + 2);
        }
        asm volatile("cp.async.commit_group;\n");

        const __nv_bfloat16* As = (const __nv_bfloat16*)(smc + s * A_BYTES);
        const float* Bs = (const float*)(smc + OFF_B + s * B_BYTES);

#pragma unroll
        for (int ks = 0; ks < 2; ks++) {
            const int k0 = ks * 16;
            uint32_t a[3][4];
#pragma unroll
            for (int mi = 0; mi < 3; mi++) {
                const int r0 = (wm * 48 + mi * 16 + g8) * APB;
                a[mi][0] = *(const uint32_t*)&As[r0 + k0 + tg * 2];
                a[mi][1] = *(const uint32_t*)&As[r0 + 8 * APB + k0 + tg * 2];
                a[mi][2] = *(const uint32_t*)&As[r0 + k0 + tg * 2 + 8];
                a[mi][3] = *(const uint32_t*)&As[r0 + 8 * APB + k0 + tg * 2 + 8];
            }
            uint32_t b[4][2];
#pragma unroll
            for (int ni = 0; ni < 4; ni++) {
                const float* bp = &Bs[(wn * 32 + ni * 8 + g8) * APB + k0 + tg * 2];
                float2 v0 = *(const float2*)bp;
                float2 v1 = *(const float2*)(bp + 8);
                b[ni][0] = bf2_bits(v0.x, v0.y);
                b[ni][1] = bf2_bits(v1.x, v1.y);
            }
#pragma unroll
            for (int mi = 0; mi < 3; mi++)
#pragma unroll
                for (int ni = 0; ni < 4; ni++) mma16(acc[mi][ni], a[mi], b[ni]);
        }
    }
#undef LOAD_STAGE

    if (!is_z) {
        // ---- per-row lse over this 128-col tile ----
        float* red_m = (float*)(smc + OFF_RED);
        float* red_s = red_m + BM * 4;
#pragma unroll
        for (int mi = 0; mi < 3; mi++) {
#pragma unroll
            for (int half = 0; half < 2; half++) {
                float v[8];
#pragma unroll
                for (int ni = 0; ni < 4; ni++) {
                    v[2 * ni]     = half ? acc[mi][ni].z : acc[mi][ni].x;
                    v[2 * ni + 1] = half ? acc[mi][ni].w : acc[mi][ni].y;
                }
                float m = v[0];
#pragma unroll
                for (int i = 1; i < 8; i++) m = fmaxf(m, v[i]);
                float s = 0.f;
#pragma unroll
                for (int i = 0; i < 8; i++) s += __expf(v[i] - m);
#pragma unroll
                for (int o = 1; o < 4; o <<= 1) {
                    float om = __shfl_xor_sync(0xffffffffu, m, o);
                    float os = __shfl_xor_sync(0xffffffffu, s, o);
                    float nm = fmaxf(m, om);
                    s = s * __expf(m - nm) + os * __expf(om - nm);
                    m = nm;
                }
                if (tg == 0) {
                    int rl = wm * 48 + mi * 16 + half * 8 + g8;
                    red_m[rl * 4 + wn] = m;
                    red_s[rl * 4 + wn] = s;
                }
            }
        }
        __syncthreads();
        if (tid < BM) {
            float m = red_m[tid * 4], s = red_s[tid * 4];
#pragma unroll
            for (int w = 1; w < 4; w++) {
                float om = red_m[tid * 4 + w], os = red_s[tid * 4 + w];
                float nm = fmaxf(m, om);
                s = s * __expf(m - nm) + os * __expf(om - nm);
                m = nm;
            }
            int grow = mtile * BM + tid;
            if (grow < NQ) d_part[grow * NT_Q + ntile] = m + __logf(s);
        }
    } else {
        // ---- write raw sims for the z-key tiles ----
        const int col0 = (ntile - NT_Q) * BN + wn * 32;
#pragma unroll
        for (int mi = 0; mi < 3; mi++) {
            const int row0 = mtile * BM + wm * 48 + mi * 16 + g8;
#pragma unroll
            for (int ni = 0; ni < 4; ni++) {
                const int c = col0 + ni * 8 + 2 * tg;
                *(float2*)&d_Sim[row0 * Nn + c]       = make_float2(acc[mi][ni].x, acc[mi][ni].y);
                *(float2*)&d_Sim[(row0 + 8) * Nn + c] = make_float2(acc[mi][ni].z, acc[mi][ni].w);
            }
        }
    }
}

// ---------------- kernel 3: fused reduce + masked lse + combine + smoothness + final ----------------
__global__ void k_post(const float* __restrict__ z, float* __restrict__ out) {
    __shared__ float rm[256], rs[256];
    __shared__ float posbuf[Ll];
    __shared__ float s_pos, s_lseq, s_lse;
    __shared__ int s_last;
    const int bid = blockIdx.x, tid = threadIdx.x;
    const bool is_g = (bid >= Nn);
    const int a = bid, gb = bid - Nn;

    // ---- phase A: lse over 1024 queue partials ----
    const float* p = d_part + bid * NT_Q;
    float vals[4];
    float m = -INFINITY;
#pragma unroll
    for (int i = 0; i < 4; i++) { vals[i] = p[tid + i * 256]; m = fmaxf(m, vals[i]); }
    rm[tid] = m; __syncthreads();
    for (int st = 128; st; st >>= 1) {
        if (tid < st) rm[tid] = fmaxf(rm[tid], rm[tid + st]);
        __syncthreads();
    }
    const float M = rm[0]; __syncthreads();
    float s = 0.f;
#pragma unroll
    for (int i = 0; i < 4; i++) s += __expf(vals[i] - M);
    rs[tid] = s; __syncthreads();
    for (int st = 128; st; st >>= 1) {
        if (tid < st) rs[tid] += rs[tid + st];
        __syncthreads();
    }
    if (tid == 0) s_lseq = M + __logf(rs[0]);
    __syncthreads();

    // ---- phase B: masked lse over the 512 precomputed sims ----
    float mm = -INFINITY, sacc = 0.f;
#pragma unroll
    for (int rep = 0; rep < 2; rep++) {
        const int j = tid + rep * 256;
        const float v = d_Sim[bid * Nn + j];
        bool masked = false;
        if (is_g) { if ((j >> 5) == gb) { posbuf[j & 31] = v; masked = true; } }
        else {
            if (j == a) masked = true;
            else if (j == a + 1) { s_pos = v; masked = true; }
        }
        if (!masked) {
            if (v > mm) { sacc = sacc * expf(mm - v) + 1.f; mm = v; }
            else        { sacc += expf(v - mm); }
        }
    }
    rm[tid] = mm; rs[tid] = sacc;
    __syncthreads();
    for (int st = 128; st; st >>= 1) {
        if (tid < st) {
            float m1 = rm[tid], s1 = rs[tid];
            float m2 = rm[tid + st], s2 = rs[tid + st];
            float nm = fmaxf(m1, m2);
            float ns = (nm == -INFINITY) ? 0.f : s1 * expf(m1 - nm) + s2 * expf(m2 - nm);
            rm[tid] = nm; rs[tid] = ns;
        }
        __syncthreads();
    }
    if (tid == 0) {
        const float lneg = rm[0] + logf(rs[0]);
        const float lq = s_lseq;
        const float hi = fmaxf(lneg, lq), lo = fminf(lneg, lq);
        s_lse = hi + log1pf(expf(lo - hi));
    }
    __syncthreads();
    if (!is_g) {
        const int t = a & (Ll - 1);
        if (t < Ll - 1 && tid == 0)
            d_llterms[(a >> 5) * (Ll - 1) + t] = softplusf(s_lse - s_pos);
    } else {
        if (tid < Ll) d_glterms[gb * Ll + tid] = softplusf(s_lse - posbuf[tid]);
    }

    // ---- phase C: per-frame smoothness partial (z blocks with t < Ll-1) ----
    if (!is_g && (a & (Ll - 1)) < Ll - 1) {
        const float df = z[(a + 1) * Dd + tid] - z[a * Dd + tid];
        __syncthreads();
        rm[tid] = df * df;
        __syncthreads();
        for (int st = 128; st; st >>= 1) {
            if (tid < st) rm[tid] += rm[tid + st];
            __syncthreads();
        }
        if (tid == 0) {
            const int t = a & (Ll - 1);
            d_smterms[(a >> 5) * (Ll - 1) + t] = rm[0];
        }
    }

    // ---- phase D: last block computes the final scalar ----
    __threadfence();
    __syncthreads();
    if (tid == 0) s_last = (atomicAdd(&d_done, 1) == NQ - 1);
    __syncthreads();
    if (s_last) {
        __threadfence();
        float sll = 0.f, sgl = 0.f, ssm = 0.f;
        for (int i = tid; i < MLL; i += 256) { sll += d_llterms[i]; ssm += d_smterms[i]; }
        for (int i = tid; i < Nn; i += 256) sgl += d_glterms[i];
        float Sll, Sgl, Ssm;
        rm[tid] = sll; __syncthreads();
        for (int st = 128; st; st >>= 1) { if (tid < st) rm[tid] += rm[tid + st]; __syncthreads(); }
        Sll = rm[0]; __syncthreads();
        rm[tid] = sgl; __syncthreads();
        for (int st = 128; st; st >>= 1) { if (tid < st) rm[tid] += rm[tid + st]; __syncthreads(); }
        Sgl = rm[0]; __syncthreads();
        rm[tid] = ssm; __syncthreads();
        for (int st = 128; st; st >>= 1) { if (tid < st) rm[tid] += rm[tid + st]; __syncthreads(); }
        Ssm = rm[0];
        if (tid == 0)
            out[0] = Sll / (float)MLL + 0.5f * (Sgl / (float)Nn) + 0.1f * (Ssm / (float)MLL);
    }
}

// ---------------- launch ----------------
extern "C" void kernel_launch(void* const* d_in, const int* in_sizes, int n_in,
                              void* d_out, int out_size) {
    const float* z  = (const float*)d_in[0];
    const float* g  = (const float*)d_in[1];
    const float* mq = (const float*)d_in[3];
    float* out = (float*)d_out;

    cudaFuncSetAttribute(k_gemm, cudaFuncAttributeMaxDynamicSharedMemorySize, SMEM_BYTES);

    k_prep<<<NQP / 4, 256>>>(z, g);
    dim3 grid(MT, NT);     // mtile fastest -> the 6 blocks sharing a key tile run together
    k_gemm<<<grid, 256, SMEM_BYTES>>>(mq, z);
    k_post<<<NQ, 256>>>(z, out);
}

// round 15
// speedup vs baseline: 1.1396x; 1.0031x over previous
#include <cuda_runtime.h>
#include <cuda_bf16.h>
#include <cstdint>
#include <math.h>

// ---------------- problem constants ----------------
#define INV_TAU (1.0f / 0.07f)
constexpr int Bb = 16, Ll = 32, Dd = 256, Kk = 131072;
constexpr int Nn = 512;          // B*L frames
constexpr int NQ = 528;          // 512 z rows + 16 g rows
constexpr int NQP = 576;         // padded to 6*96
constexpr int BM = 96, BN = 128, BK = 32;
constexpr int NT_Q = Kk / BN;    // 1024 queue tiles
constexpr int NT_Z = Nn / BN;    // 4 z-key tiles
constexpr int NT = NT_Q + NT_Z;  // 1028
constexpr int MT = NQP / BM;     // 6
constexpr int MLL = Bb * (Ll - 1);

// smem layout: A bf16 pitch 40 (80B rows), B fp32 pitch 40 (160B rows); 3 stages
constexpr int APB = 40;                       // elems per row slot
constexpr int A_BYTES = BM * APB * 2;         // 7680 per stage
constexpr int B_BYTES = BN * APB * 4;         // 20480 per stage (fp32)
constexpr int OFF_B = 3 * A_BYTES;            // 23040
constexpr int OFF_RED = OFF_B + 3 * B_BYTES;  // 84480
constexpr int SMEM_BYTES = OFF_RED + BM * 4 * 4 * 2;  // + red[96][4]x2 = 87552 (85.5KB)

// ---------------- device scratch ----------------
__device__ __nv_bfloat16 d_Qbuf[NQP * Dd];    // scaled bf16 queries
__device__ float d_part[NQP * NT_Q];
__device__ float d_Sim[NQP * Nn];
__device__ float d_llterms[MLL];
__device__ float d_glterms[Nn];
__device__ float d_smterms[Nn];               // per-frame smoothness partials
__device__ int d_done;                        // k_post completion counter

// ---------------- helpers ----------------
__device__ __forceinline__ void mma16(float4& d, const uint32_t* a, const uint32_t* b) {
    asm volatile(
        "mma.sync.aligned.m16n8k16.row.col.f32.bf16.bf16.f32 "
        "{%0,%1,%2,%3}, {%4,%5,%6,%7}, {%8,%9}, {%0,%1,%2,%3};\n"
        : "+f"(d.x), "+f"(d.y), "+f"(d.z), "+f"(d.w)
        : "r"(a[0]), "r"(a[1]), "r"(a[2]), "r"(a[3]), "r"(b[0]), "r"(b[1]));
}
__device__ __forceinline__ void cpasync16(uint32_t dst, const void* src) {
    asm volatile("cp.async.cg.shared.global [%0], [%1], 16;\n" :: "r"(dst), "l"(src));
}
__device__ __forceinline__ float softplusf(float x) {
    return (x > 0.f) ? x + log1pf(expf(-x)) : log1pf(expf(x));
}
__device__ __forceinline__ uint32_t bf2_bits(float lo, float hi) {
    __nv_bfloat162 p = __float22bfloat162_rn(make_float2(lo, hi));
    return *reinterpret_cast<uint32_t*>(&p);
}
// lse-merge of (m, s) pairs
__device__ __forceinline__ void lse_merge(float& m, float& s, float om, float os) {
    float nm = fmaxf(m, om);
    s = (nm == -INFINITY) ? 0.f : s * __expf(m - nm) + os * __expf(om - nm);
    m = nm;
}

// ---------------- kernel 1: queries (scaled) -> bf16 (vectorized) ----------------
__global__ void k_prep(const float* __restrict__ z, const float* __restrict__ g) {
    const int i = blockIdx.x * blockDim.x + threadIdx.x;   // handles 4 elems
    if (i == 0) d_done = 0;                                // reset fusion counter
    const int e = i * 4;
    const int row = e >> 8, d = e & 255;
    float4 v = make_float4(0.f, 0.f, 0.f, 0.f);
    if (row < Nn)       v = *(const float4*)(z + e);
    else if (row < NQ)  v = *(const float4*)(g + (row - Nn) * Dd + d);
    v.x *= INV_TAU; v.y *= INV_TAU; v.z *= INV_TAU; v.w *= INV_TAU;
    uint2 o;
    o.x = bf2_bits(v.x, v.y);
    o.y = bf2_bits(v.z, v.w);
    *(uint2*)(d_Qbuf + e) = o;
}

// ---------------- kernel 2: 3-stage pipelined bf16 GEMM, 2 CTAs/SM ----------------
__global__ __launch_bounds__(256, 2) void k_gemm(const float* __restrict__ mq,
                                                 const float* __restrict__ zk) {
    extern __shared__ char smc[];
    const uint32_t smem_u32 = (uint32_t)__cvta_generic_to_shared(smc);

    const int tid  = threadIdx.x;
    const int warp = tid >> 5, lane = tid & 31;
    const int wm = warp >> 2, wn = warp & 3;   // 2 x 4 warp grid (48 rows x 32 cols each)
    const int g8 = lane >> 2, tg = lane & 3;
    const int mtile = blockIdx.x;
    const int ntile = blockIdx.y;
    const bool is_z = (ntile >= NT_Q);

    const __nv_bfloat16* Qb = d_Qbuf + mtile * BM * Dd;
    const float* Kb = is_z ? (zk + (size_t)(ntile - NT_Q) * BN * Dd)
                           : (mq + (size_t)ntile * BN * Dd);

    float4 acc[3][4];
#pragma unroll
    for (int mi = 0; mi < 3; mi++)
#pragma unroll
        for (int ni = 0; ni < 4; ni++) acc[mi][ni] = make_float4(0.f, 0.f, 0.f, 0.f);

    // A: 96x32 bf16 = 384 x16B (1.5/thread). B: 128x32 fp32 = 1024 x16B (4/thread).
#define LOAD_STAGE(s, kk)                                                            \
    do {                                                                             \
        _Pragma("unroll")                                                            \
        for (int i = 0; i < 2; i++) {                                                \
            int id = tid + i * 256;                                                  \
            if (id < 384) {                                                          \
                int r = id >> 2, c8 = id & 3;                                        \
                uint32_t dst = smem_u32 + (s) * A_BYTES + (r * APB + c8 * 8) * 2;    \
                cpasync16(dst, Qb + r * Dd + (kk) * BK + c8 * 8);                    \
            }                                                                        \
        }                                                                            \
        _Pragma("unroll")                                                            \
        for (int i = 0; i < 4; i++) {                                                \
            int id = tid + i * 256; int r = id >> 3, c4 = id & 7;                    \
            uint32_t dst = smem_u32 + OFF_B + (s) * B_BYTES + (r * APB + c4 * 4) * 4; \
            cpasync16(dst, Kb + r * Dd + (kk) * BK + c4 * 4);                        \
        }                                                                            \
    } while (0)

    LOAD_STAGE(0, 0);
    asm volatile("cp.async.commit_group;\n");
    LOAD_STAGE(1, 1);
    asm volatile("cp.async.commit_group;\n");

#pragma unroll
    for (int kk = 0; kk < 8; kk++) {
        asm volatile("cp.async.wait_group 1;\n");
        __syncthreads();
        const int s = kk % 3;
        if (kk + 2 < 8) {
            LOAD_STAGE((kk + 2) % 3, kk + 2);
        }
        asm volatile("cp.async.commit_group;\n");

        const __nv_bfloat16* As = (const __nv_bfloat16*)(smc + s * A_BYTES);
        const float* Bs = (const float*)(smc + OFF_B + s * B_BYTES);

#pragma unroll
        for (int ks = 0; ks < 2; ks++) {
            const int k0 = ks * 16;
            uint32_t a[3][4];
#pragma unroll
            for (int mi = 0; mi < 3; mi++) {
                const int r0 = (wm * 48 + mi * 16 + g8) * APB;
                a[mi][0] = *(const uint32_t*)&As[r0 + k0 + tg * 2];
                a[mi][1] = *(const uint32_t*)&As[r0 + 8 * APB + k0 + tg * 2];
                a[mi][2] = *(const uint32_t*)&As[r0 + k0 + tg * 2 + 8];
                a[mi][3] = *(const uint32_t*)&As[r0 + 8 * APB + k0 + tg * 2 + 8];
            }
            uint32_t b[4][2];
#pragma unroll
            for (int ni = 0; ni < 4; ni++) {
                const float* bp = &Bs[(wn * 32 + ni * 8 + g8) * APB + k0 + tg * 2];
                float2 v0 = *(const float2*)bp;
                float2 v1 = *(const float2*)(bp + 8);
                b[ni][0] = bf2_bits(v0.x, v0.y);
                b[ni][1] = bf2_bits(v1.x, v1.y);
            }
#pragma unroll
            for (int mi = 0; mi < 3; mi++)
#pragma unroll
                for (int ni = 0; ni < 4; ni++) mma16(acc[mi][ni], a[mi], b[ni]);
        }
    }
#undef LOAD_STAGE

    if (!is_z) {
        // ---- per-row lse over this 128-col tile ----
        float* red_m = (float*)(smc + OFF_RED);
        float* red_s = red_m + BM * 4;
#pragma unroll
        for (int mi = 0; mi < 3; mi++) {
#pragma unroll
            for (int half = 0; half < 2; half++) {
                float v[8];
#pragma unroll
                for (int ni = 0; ni < 4; ni++) {
                    v[2 * ni]     = half ? acc[mi][ni].z : acc[mi][ni].x;
                    v[2 * ni + 1] = half ? acc[mi][ni].w : acc[mi][ni].y;
                }
                float m = v[0];
#pragma unroll
                for (int i = 1; i < 8; i++) m = fmaxf(m, v[i]);
                float s = 0.f;
#pragma unroll
                for (int i = 0; i < 8; i++) s += __expf(v[i] - m);
#pragma unroll
                for (int o = 1; o < 4; o <<= 1) {
                    float om = __shfl_xor_sync(0xffffffffu, m, o);
                    float os = __shfl_xor_sync(0xffffffffu, s, o);
                    float nm = fmaxf(m, om);
                    s = s * __expf(m - nm) + os * __expf(om - nm);
                    m = nm;
                }
                if (tg == 0) {
                    int rl = wm * 48 + mi * 16 + half * 8 + g8;
                    red_m[rl * 4 + wn] = m;
                    red_s[rl * 4 + wn] = s;
                }
            }
        }
        __syncthreads();
        if (tid < BM) {
            float m = red_m[tid * 4], s = red_s[tid * 4];
#pragma unroll
            for (int w = 1; w < 4; w++) {
                float om = red_m[tid * 4 + w], os = red_s[tid * 4 + w];
                float nm = fmaxf(m, om);
                s = s * __expf(m - nm) + os * __expf(om - nm);
                m = nm;
            }
            int grow = mtile * BM + tid;
            if (grow < NQ) d_part[grow * NT_Q + ntile] = m + __logf(s);
        }
    } else {
        // ---- write raw sims for the z-key tiles ----
        const int col0 = (ntile - NT_Q) * BN + wn * 32;
#pragma unroll
        for (int mi = 0; mi < 3; mi++) {
            const int row0 = mtile * BM + wm * 48 + mi * 16 + g8;
#pragma unroll
            for (int ni = 0; ni < 4; ni++) {
                const int c = col0 + ni * 8 + 2 * tg;
                *(float2*)&d_Sim[row0 * Nn + c]       = make_float2(acc[mi][ni].x, acc[mi][ni].y);
                *(float2*)&d_Sim[(row0 + 8) * Nn + c] = make_float2(acc[mi][ni].z, acc[mi][ni].w);
            }
        }
    }
}

// ---------------- kernel 3: fused post (shuffle reductions, minimal barriers) ----------------
__global__ void k_post(const float* __restrict__ z, float* __restrict__ out) {
    __shared__ float wm_[8], ws_[8];           // per-warp partials
    __shared__ float posbuf[Ll];
    __shared__ float s_pos, s_lseq, s_lse;
    __shared__ int s_last;
    const int bid = blockIdx.x, tid = threadIdx.x;
    const int warp = tid >> 5, lane = tid & 31;
    const bool is_g = (bid >= Nn);
    const int a = bid, gb = bid - Nn;

    // ---- phase A: lse over 1024 queue partials (warp-shuffle reduce) ----
    {
        const float* p = d_part + bid * NT_Q;
        float m = -INFINITY, s = 0.f;
#pragma unroll
        for (int i = 0; i < 4; i++) {
            float v = p[tid + i * 256];
            if (v > m) { s = s * __expf(m - v) + 1.f; m = v; }
            else       { s += __expf(v - m); }
        }
#pragma unroll
        for (int o = 16; o; o >>= 1)
            lse_merge(m, s, __shfl_xor_sync(0xffffffffu, m, o),
                            __shfl_xor_sync(0xffffffffu, s, o));
        if (lane == 0) { wm_[warp] = m; ws_[warp] = s; }
        __syncthreads();
        if (warp == 0) {
            float mm = (lane < 8) ? wm_[lane] : -INFINITY;
            float ss = (lane < 8) ? ws_[lane] : 0.f;
#pragma unroll
            for (int o = 4; o; o >>= 1)
                lse_merge(mm, ss, __shfl_xor_sync(0xffffffffu, mm, o),
                                  __shfl_xor_sync(0xffffffffu, ss, o));
            if (lane == 0) s_lseq = mm + __logf(ss);
        }
    }
    __syncthreads();

    // ---- phase B: masked lse over the 512 precomputed sims ----
    {
        float m = -INFINITY, s = 0.f;
#pragma unroll
        for (int rep = 0; rep < 2; rep++) {
            const int j = tid + rep * 256;
            const float v = d_Sim[bid * Nn + j];
            bool masked = false;
            if (is_g) { if ((j >> 5) == gb) { posbuf[j & 31] = v; masked = true; } }
            else {
                if (j == a) masked = true;
                else if (j == a + 1) { s_pos = v; masked = true; }
            }
            if (!masked) {
                if (v > m) { s = s * __expf(m - v) + 1.f; m = v; }
                else       { s += __expf(v - m); }
            }
        }
#pragma unroll
        for (int o = 16; o; o >>= 1)
            lse_merge(m, s, __shfl_xor_sync(0xffffffffu, m, o),
                            __shfl_xor_sync(0xffffffffu, s, o));
        if (lane == 0) { wm_[warp] = m; ws_[warp] = s; }
        __syncthreads();
        if (warp == 0) {
            float mm = (lane < 8) ? wm_[lane] : -INFINITY;
            float ss = (lane < 8) ? ws_[lane] : 0.f;
#pragma unroll
            for (int o = 4; o; o >>= 1)
                lse_merge(mm, ss, __shfl_xor_sync(0xffffffffu, mm, o),
                                  __shfl_xor_sync(0xffffffffu, ss, o));
            if (lane == 0) {
                const float lneg = mm + __logf(ss);
                const float lq = s_lseq;
                const float hi = fmaxf(lneg, lq), lo = fminf(lneg, lq);
                s_lse = hi + log1pf(expf(lo - hi));
            }
        }
    }
    __syncthreads();

    if (!is_g) {
        const int t = a & (Ll - 1);
        if (t < Ll - 1 && tid == 0)
            d_llterms[(a >> 5) * (Ll - 1) + t] = softplusf(s_lse - s_pos);
    } else {
        if (tid < Ll) d_glterms[gb * Ll + tid] = softplusf(s_lse - posbuf[tid]);
    }

    // ---- phase C: per-frame smoothness partial (z blocks with t < Ll-1) ----
    if (!is_g && (a & (Ll - 1)) < Ll - 1) {
        const float df = z[(a + 1) * Dd + tid] - z[a * Dd + tid];
        float s = df * df;
#pragma unroll
        for (int o = 16; o; o >>= 1) s += __shfl_xor_sync(0xffffffffu, s, o);
        if (lane == 0) ws_[warp] = s;
        __syncthreads();
        if (warp == 0) {
            float ss = (lane < 8) ? ws_[lane] : 0.f;
#pragma unroll
            for (int o = 4; o; o >>= 1) ss += __shfl_xor_sync(0xffffffffu, ss, o);
            if (lane == 0) {
                const int t = a & (Ll - 1);
                d_smterms[(a >> 5) * (Ll - 1) + t] = ss;
            }
        }
    }

    // ---- phase D: last block computes the final scalar ----
    __threadfence();
    __syncthreads();
    if (tid == 0) s_last = (atomicAdd(&d_done, 1) == NQ - 1);
    __syncthreads();
    if (s_last) {
        __threadfence();
        float sll = 0.f, sgl = 0.f, ssm = 0.f;
        for (int i = tid; i < MLL; i += 256) { sll += d_llterms[i]; ssm += d_smterms[i]; }
        for (int i = tid; i < Nn; i += 256) sgl += d_glterms[i];
#pragma unroll
        for (int o = 16; o; o >>= 1) {
            sll += __shfl_xor_sync(0xffffffffu, sll, o);
            sgl += __shfl_xor_sync(0xffffffffu, sgl, o);
            ssm += __shfl_xor_sync(0xffffffffu, ssm, o);
        }
        if (lane == 0) { wm_[warp] = sll; ws_[warp] = sgl; posbuf[warp] = ssm; }
        __syncthreads();
        if (tid == 0) {
            float Sll = 0.f, Sgl = 0.f, Ssm = 0.f;
#pragma unroll
            for (int w = 0; w < 8; w++) { Sll += wm_[w]; Sgl += ws_[w]; Ssm += posbuf[w]; }
            out[0] = Sll / (float)MLL + 0.5f * (Sgl / (float)Nn) + 0.1f * (Ssm / (float)MLL);
        }
    }
}

// ---------------- launch ----------------
extern "C" void kernel_launch(void* const* d_in, const int* in_sizes, int n_in,
                              void* d_out, int out_size) {
    const float* z  = (const float*)d_in[0];
    const float* g  = (const float*)d_in[1];
    const float* mq = (const float*)d_in[3];
    float* out = (float*)d_out;

    cudaFuncSetAttribute(k_gemm, cudaFuncAttributeMaxDynamicSharedMemorySize, SMEM_BYTES);

    k_prep<<<NQP / 4, 256>>>(z, g);
    dim3 grid(MT, NT);     // mtile fastest -> the 6 blocks sharing a key tile run together
    k_gemm<<<grid, 256, SMEM_BYTES>>>(mq, z);
    k_post<<<NQ, 256>>>(z, out);
}